// round 4
// baseline (speedup 1.0000x reference)
#include <cuda_runtime.h>
#include <cuda_bf16.h>

#define N_NODES 50000
#define N_EDGES 800000
#define D 128
#define N_GRAPHS 128
#define OUT_DIM 16

// Scratch (no cudaMalloc allowed): ping-pong feature buffers + aggregation buffer.
__device__ float g_agg[N_NODES * D];
__device__ float g_hA[N_NODES * D];
__device__ float g_hB[N_NODES * D];
__device__ float g_sums[N_GRAPHS * D];
__device__ float g_cnt[N_GRAPHS];

// ---------------------------------------------------------------------------
// Zero kernels
// ---------------------------------------------------------------------------
__global__ void k_zero_agg() {
    float4* p = reinterpret_cast<float4*>(g_agg);
    int n4 = (N_NODES * D) / 4;
    for (int i = blockIdx.x * blockDim.x + threadIdx.x; i < n4; i += gridDim.x * blockDim.x)
        p[i] = make_float4(0.f, 0.f, 0.f, 0.f);
}

__global__ void k_zero_pool() {
    int i = blockIdx.x * blockDim.x + threadIdx.x;
    if (i < N_GRAPHS * D) g_sums[i] = 0.f;
    if (i < N_GRAPHS) g_cnt[i] = 0.f;
}

// ---------------------------------------------------------------------------
// Edge scatter: agg[dst] += h[src].  One warp per edge, 4 edges per warp.
// Vectorized global reduction (red.global.add.v4.f32) -> 32 REDs per edge.
// NOTE: edge_index is int32 (JAX x64-disabled downcasts the requested int64).
// ---------------------------------------------------------------------------
#define EDGES_PER_WARP 4
__global__ __launch_bounds__(256) void k_scatter(const float* __restrict__ h,
                                                 const int* __restrict__ ei) {
    int gwarp = (blockIdx.x * blockDim.x + threadIdx.x) >> 5;
    int lane = threadIdx.x & 31;
    int e0 = gwarp * EDGES_PER_WARP;
#pragma unroll
    for (int i = 0; i < EDGES_PER_WARP; i++) {
        int e = e0 + i;
        if (e >= N_EDGES) return;
        int src = ei[e];
        int dst = ei[N_EDGES + e];
        const float4 v = *reinterpret_cast<const float4*>(h + (long long)src * D + lane * 4);
        float* dp = g_agg + (long long)dst * D + lane * 4;
        asm volatile("red.global.add.v4.f32 [%0], {%1,%2,%3,%4};"
                     :: "l"(dp), "f"(v.x), "f"(v.y), "f"(v.z), "f"(v.w)
                     : "memory");
    }
}

// ---------------------------------------------------------------------------
// Fused GraphConv update:
//   hout = relu( g_agg @ Wrel + hin @ Wroot + brel )
// Tile: 64 rows x 128 cols per block, 256 threads, thread tile 8x4.
// Both 128x128 weight matrices + A/H tiles live in shared (192KB dyn smem).
// ---------------------------------------------------------------------------
#define BM 64
#define GEMM_SMEM_FLOATS (2 * D * D + 2 * BM * D + D)
#define GEMM_SMEM_BYTES (GEMM_SMEM_FLOATS * 4)

__global__ __launch_bounds__(256, 1) void k_gemm(const float* __restrict__ hin,
                                                 const float* __restrict__ Wrel,
                                                 const float* __restrict__ brel,
                                                 const float* __restrict__ Wroot,
                                                 float* __restrict__ hout) {
    extern __shared__ float smem[];
    float* sWrel = smem;                 // 128*128
    float* sWroot = smem + D * D;        // 128*128
    float* sA = smem + 2 * D * D;        // 64*128
    float* sH = sA + BM * D;             // 64*128
    float* sb = sH + BM * D;             // 128

    int tid = threadIdx.x;
    int tx = tid & 31;      // column group: cols [tx*4, tx*4+3]
    int ty = tid >> 5;      // row group:    rows [ty*8, ty*8+7]
    int row0 = blockIdx.x * BM;

    // Load weights (coalesced float4)
    {
        const float4* wr4 = reinterpret_cast<const float4*>(Wrel);
        const float4* wo4 = reinterpret_cast<const float4*>(Wroot);
        float4* sr4 = reinterpret_cast<float4*>(sWrel);
        float4* so4 = reinterpret_cast<float4*>(sWroot);
#pragma unroll
        for (int i = 0; i < (D * D / 4) / 256; i++) {
            int idx = i * 256 + tid;
            sr4[idx] = wr4[idx];
            so4[idx] = wo4[idx];
        }
        if (tid < 32) reinterpret_cast<float4*>(sb)[tid] =
            reinterpret_cast<const float4*>(brel)[tid];
    }

    // Load A (agg) and H (residual input) tiles, zero-padded past N_NODES.
    {
        float4* sA4 = reinterpret_cast<float4*>(sA);
        float4* sH4 = reinterpret_cast<float4*>(sH);
#pragma unroll
        for (int i = 0; i < (BM * D / 4) / 256; i++) {
            int idx = i * 256 + tid;           // float4 index within tile
            int r = idx >> 5;                  // D/4 = 32 float4 per row
            int row = row0 + r;
            if (row < N_NODES) {
                sA4[idx] = reinterpret_cast<const float4*>(g_agg)[row * 32 + (idx & 31)];
                sH4[idx] = reinterpret_cast<const float4*>(hin)[(long long)row * 32 + (idx & 31)];
            } else {
                sA4[idx] = make_float4(0.f, 0.f, 0.f, 0.f);
                sH4[idx] = make_float4(0.f, 0.f, 0.f, 0.f);
            }
        }
    }
    __syncthreads();

    float acc[8][4];
#pragma unroll
    for (int r = 0; r < 8; r++)
#pragma unroll
        for (int c = 0; c < 4; c++) acc[r][c] = 0.f;

#pragma unroll 8
    for (int k = 0; k < D; k++) {
        float4 wr = *reinterpret_cast<const float4*>(&sWrel[k * D + tx * 4]);
        float4 wo = *reinterpret_cast<const float4*>(&sWroot[k * D + tx * 4]);
#pragma unroll
        for (int r = 0; r < 8; r++) {
            float a = sA[(ty * 8 + r) * D + k];   // warp-uniform broadcast
            float hh = sH[(ty * 8 + r) * D + k];
            acc[r][0] += a * wr.x + hh * wo.x;
            acc[r][1] += a * wr.y + hh * wo.y;
            acc[r][2] += a * wr.z + hh * wo.z;
            acc[r][3] += a * wr.w + hh * wo.w;
        }
    }

    // Epilogue: bias + relu, vectorized store
    float4 bias = *reinterpret_cast<const float4*>(&sb[tx * 4]);
#pragma unroll
    for (int r = 0; r < 8; r++) {
        int row = row0 + ty * 8 + r;
        if (row < N_NODES) {
            float4 o;
            o.x = fmaxf(acc[r][0] + bias.x, 0.f);
            o.y = fmaxf(acc[r][1] + bias.y, 0.f);
            o.z = fmaxf(acc[r][2] + bias.z, 0.f);
            o.w = fmaxf(acc[r][3] + bias.w, 0.f);
            *reinterpret_cast<float4*>(&hout[(long long)row * D + tx * 4]) = o;
        }
    }
}

// ---------------------------------------------------------------------------
// Global mean pool: sums[g] += h[n], cnt[g] += 1.  One warp per node.
// batch_ids is int32 (same JAX downcast as edge_index).
// ---------------------------------------------------------------------------
#define NODES_PER_WARP 4
__global__ __launch_bounds__(256) void k_pool(const float* __restrict__ h,
                                              const int* __restrict__ batch) {
    int gwarp = (blockIdx.x * blockDim.x + threadIdx.x) >> 5;
    int lane = threadIdx.x & 31;
#pragma unroll
    for (int i = 0; i < NODES_PER_WARP; i++) {
        int n = gwarp * NODES_PER_WARP + i;
        if (n >= N_NODES) return;
        int g = batch[n];
        const float4 v = *reinterpret_cast<const float4*>(h + (long long)n * D + lane * 4);
        float* dp = g_sums + g * D + lane * 4;
        asm volatile("red.global.add.v4.f32 [%0], {%1,%2,%3,%4};"
                     :: "l"(dp), "f"(v.x), "f"(v.y), "f"(v.z), "f"(v.w)
                     : "memory");
        if (lane == 0) atomicAdd(&g_cnt[g], 1.0f);
    }
}

// ---------------------------------------------------------------------------
// MLP head: out[g] = (pooled[g] @ W1 + b1) @ W2 + b2  (no relu).
// One block per graph.
// ---------------------------------------------------------------------------
__global__ __launch_bounds__(128) void k_head(const float* __restrict__ W1,
                                              const float* __restrict__ b1,
                                              const float* __restrict__ W2,
                                              const float* __restrict__ b2,
                                              float* __restrict__ out) {
    __shared__ float pooled[D];
    __shared__ float t[D];
    int g = blockIdx.x;
    int tid = threadIdx.x;
    float cnt = fmaxf(g_cnt[g], 1.0f);
    pooled[tid] = g_sums[g * D + tid] / cnt;
    __syncthreads();

    float acc = b1[tid];
#pragma unroll 8
    for (int k = 0; k < D; k++) acc += pooled[k] * W1[k * D + tid];
    t[tid] = acc;
    __syncthreads();

    if (tid < OUT_DIM) {
        float o = b2[tid];
#pragma unroll 8
        for (int k = 0; k < D; k++) o += t[k] * W2[k * OUT_DIM + tid];
        out[g * OUT_DIM + tid] = o;
    }
}

// ---------------------------------------------------------------------------
// Launch sequence (graph-capturable: kernel launches only)
// ---------------------------------------------------------------------------
extern "C" void kernel_launch(void* const* d_in, const int* in_sizes, int n_in,
                              void* d_out, int out_size) {
    const float* x = (const float*)d_in[0];
    const int* ei = (const int*)d_in[1];      // int32 (JAX x64 disabled)
    const int* batch = (const int*)d_in[2];   // int32
    const float* Wrel = (const float*)d_in[3];
    const float* brel = (const float*)d_in[4];
    const float* Wroot = (const float*)d_in[5];
    const float* W1 = (const float*)d_in[6];
    const float* b1 = (const float*)d_in[7];
    const float* W2 = (const float*)d_in[8];
    const float* b2 = (const float*)d_in[9];
    float* out = (float*)d_out;

    cudaFuncSetAttribute(k_gemm, cudaFuncAttributeMaxDynamicSharedMemorySize,
                         GEMM_SMEM_BYTES);

    float* hA;
    float* hB;
    cudaGetSymbolAddress((void**)&hA, g_hA);
    cudaGetSymbolAddress((void**)&hB, g_hB);

    const int scatter_blocks = (N_EDGES + 8 * EDGES_PER_WARP - 1) / (8 * EDGES_PER_WARP);
    const int gemm_blocks = (N_NODES + BM - 1) / BM;
    const int pool_blocks = (N_NODES + 8 * NODES_PER_WARP - 1) / (8 * NODES_PER_WARP);

    // Layer 0: x -> hB
    k_zero_agg<<<2048, 256>>>();
    k_scatter<<<scatter_blocks, 256>>>(x, ei);
    k_gemm<<<gemm_blocks, 256, GEMM_SMEM_BYTES>>>(x, Wrel, brel, Wroot, hB);

    // Layer 1: hB -> hA
    k_zero_agg<<<2048, 256>>>();
    k_scatter<<<scatter_blocks, 256>>>(hB, ei);
    k_gemm<<<gemm_blocks, 256, GEMM_SMEM_BYTES>>>(hB, Wrel + D * D, brel + D,
                                                  Wroot + D * D, hA);

    // Layer 2: hA -> hB
    k_zero_agg<<<2048, 256>>>();
    k_scatter<<<scatter_blocks, 256>>>(hA, ei);
    k_gemm<<<gemm_blocks, 256, GEMM_SMEM_BYTES>>>(hA, Wrel + 2 * D * D, brel + 2 * D,
                                                  Wroot + 2 * D * D, hB);

    // Pool + head
    k_zero_pool<<<(N_GRAPHS * D + 255) / 256, 256>>>();
    k_pool<<<pool_blocks, 256>>>(hB, batch);
    k_head<<<N_GRAPHS, 128>>>(W1, b1, W2, b2, out);
}

// round 5
// speedup vs baseline: 1.5167x; 1.5167x over previous
#include <cuda_runtime.h>
#include <cuda_bf16.h>

#define N_NODES 50000
#define N_EDGES 800000
#define D 128
#define N_GRAPHS 128
#define OUT_DIM 16

// Scan decomposition: 256 blocks x CHUNK nodes
#define SCAN_BLOCKS 256
#define CHUNK 196   // 256*196 = 50176 >= N_NODES

// Scratch (no cudaMalloc allowed)
__device__ float g_agg[N_NODES * D];
__device__ float g_hA[N_NODES * D];
__device__ float g_hB[N_NODES * D];
__device__ float g_sums[N_GRAPHS * D];
__device__ float g_cnt[N_GRAPHS];
// CSR build
__device__ int g_cnt_i[N_NODES];
__device__ int g_rowptr[N_NODES];
__device__ int g_cursor[N_NODES];
__device__ int g_csr_src[N_EDGES];
__device__ int g_blocksum[SCAN_BLOCKS];
__device__ int g_blockoff[SCAN_BLOCKS];

// ---------------------------------------------------------------------------
// CSR construction (once per launch, reused by all 3 layers)
// ---------------------------------------------------------------------------
__global__ void k_csr_zero() {
    int i = blockIdx.x * blockDim.x + threadIdx.x;
    if (i < N_NODES) g_cnt_i[i] = 0;
}

__global__ void k_hist(const int* __restrict__ ei) {
    int e = blockIdx.x * blockDim.x + threadIdx.x;
    if (e < N_EDGES) atomicAdd(&g_cnt_i[ei[N_EDGES + e]], 1);
}

__global__ __launch_bounds__(256) void k_scan1() {
    __shared__ int sm[256];
    int b = blockIdx.x, t = threadIdx.x;
    int n = b * CHUNK + t;
    int v = (t < CHUNK && n < N_NODES) ? g_cnt_i[n] : 0;
    sm[t] = v;
    __syncthreads();
#pragma unroll
    for (int off = 1; off < 256; off <<= 1) {
        int x = (t >= off) ? sm[t - off] : 0;
        __syncthreads();
        sm[t] += x;
        __syncthreads();
    }
    if (t < CHUNK && n < N_NODES) g_rowptr[n] = sm[t] - v;  // exclusive
    if (t == 255) g_blocksum[b] = sm[255];
}

__global__ __launch_bounds__(256) void k_scan2() {
    __shared__ int sm[256];
    int t = threadIdx.x;
    int v = g_blocksum[t];
    sm[t] = v;
    __syncthreads();
#pragma unroll
    for (int off = 1; off < 256; off <<= 1) {
        int x = (t >= off) ? sm[t - off] : 0;
        __syncthreads();
        sm[t] += x;
        __syncthreads();
    }
    g_blockoff[t] = sm[t] - v;  // exclusive
}

__global__ __launch_bounds__(256) void k_scan3() {
    int b = blockIdx.x, t = threadIdx.x;
    int n = b * CHUNK + t;
    if (t < CHUNK && n < N_NODES) {
        int r = g_rowptr[n] + g_blockoff[b];
        g_rowptr[n] = r;
        g_cursor[n] = r;
    }
}

__global__ void k_fill(const int* __restrict__ ei) {
    int e = blockIdx.x * blockDim.x + threadIdx.x;
    if (e < N_EDGES) {
        int dst = ei[N_EDGES + e];
        int p = atomicAdd(&g_cursor[dst], 1);
        g_csr_src[p] = ei[e];
    }
}

// ---------------------------------------------------------------------------
// CSR gather: agg[n] = sum_{s in neigh(n)} h[s].  One warp per node.
// Lane l owns float4 chunk l. 4-way unrolled for MLP.
// ---------------------------------------------------------------------------
__global__ __launch_bounds__(256) void k_gather(const float* __restrict__ h) {
    int n = (blockIdx.x * blockDim.x + threadIdx.x) >> 5;
    if (n >= N_NODES) return;
    int lane = threadIdx.x & 31;
    int i = g_rowptr[n];
    int end = i + g_cnt_i[n];
    float4 acc = make_float4(0.f, 0.f, 0.f, 0.f);
    for (; i + 4 <= end; i += 4) {
        int s0 = g_csr_src[i];
        int s1 = g_csr_src[i + 1];
        int s2 = g_csr_src[i + 2];
        int s3 = g_csr_src[i + 3];
        float4 v0 = *reinterpret_cast<const float4*>(h + (long long)s0 * D + lane * 4);
        float4 v1 = *reinterpret_cast<const float4*>(h + (long long)s1 * D + lane * 4);
        float4 v2 = *reinterpret_cast<const float4*>(h + (long long)s2 * D + lane * 4);
        float4 v3 = *reinterpret_cast<const float4*>(h + (long long)s3 * D + lane * 4);
        acc.x += v0.x + v1.x + v2.x + v3.x;
        acc.y += v0.y + v1.y + v2.y + v3.y;
        acc.z += v0.z + v1.z + v2.z + v3.z;
        acc.w += v0.w + v1.w + v2.w + v3.w;
    }
    for (; i < end; i++) {
        int s = g_csr_src[i];
        float4 v = *reinterpret_cast<const float4*>(h + (long long)s * D + lane * 4);
        acc.x += v.x; acc.y += v.y; acc.z += v.z; acc.w += v.w;
    }
    *reinterpret_cast<float4*>(g_agg + (long long)n * D + lane * 4) = acc;
}

// ---------------------------------------------------------------------------
// Fused GraphConv update with packed f32x2 FMAs:
//   hout = relu( g_agg @ Wrel + hin @ Wroot + brel )
// 64 rows x 128 cols per block, 256 threads, thread tile 8 rows x 4 cols.
// Accumulators are packed f32x2 pairs over column pairs.
// ---------------------------------------------------------------------------
#define BM 64
#define GEMM_SMEM_FLOATS (2 * D * D + 2 * BM * D + D)
#define GEMM_SMEM_BYTES (GEMM_SMEM_FLOATS * 4)

__device__ __forceinline__ void fma2(unsigned long long& acc,
                                     unsigned long long a,
                                     unsigned long long b) {
    asm("fma.rn.f32x2 %0, %1, %2, %0;" : "+l"(acc) : "l"(a), "l"(b));
}
__device__ __forceinline__ unsigned long long splat2(float v) {
    unsigned long long o;
    unsigned int u = __float_as_uint(v);
    asm("mov.b64 %0, {%1, %1};" : "=l"(o) : "r"(u));
    return o;
}
__device__ __forceinline__ float2 unpack2(unsigned long long p) {
    unsigned int lo, hi;
    asm("mov.b64 {%0, %1}, %2;" : "=r"(lo), "=r"(hi) : "l"(p));
    return make_float2(__uint_as_float(lo), __uint_as_float(hi));
}

__global__ __launch_bounds__(256, 1) void k_gemm(const float* __restrict__ hin,
                                                 const float* __restrict__ Wrel,
                                                 const float* __restrict__ brel,
                                                 const float* __restrict__ Wroot,
                                                 float* __restrict__ hout) {
    extern __shared__ float smem[];
    float* sWrel = smem;                 // 128*128
    float* sWroot = smem + D * D;        // 128*128
    float* sA = smem + 2 * D * D;        // 64*128
    float* sH = sA + BM * D;             // 64*128
    float* sb = sH + BM * D;             // 128

    int tid = threadIdx.x;
    int tx = tid & 31;      // column group: cols [tx*4, tx*4+3]
    int ty = tid >> 5;      // row group:    rows [ty*8, ty*8+7]
    int row0 = blockIdx.x * BM;

    // Load weights (coalesced float4)
    {
        const float4* wr4 = reinterpret_cast<const float4*>(Wrel);
        const float4* wo4 = reinterpret_cast<const float4*>(Wroot);
        float4* sr4 = reinterpret_cast<float4*>(sWrel);
        float4* so4 = reinterpret_cast<float4*>(sWroot);
#pragma unroll
        for (int i = 0; i < (D * D / 4) / 256; i++) {
            int idx = i * 256 + tid;
            sr4[idx] = wr4[idx];
            so4[idx] = wo4[idx];
        }
        if (tid < 32) reinterpret_cast<float4*>(sb)[tid] =
            reinterpret_cast<const float4*>(brel)[tid];
    }

    // Load A (agg) and H (residual input) tiles, zero-padded past N_NODES.
    {
        float4* sA4 = reinterpret_cast<float4*>(sA);
        float4* sH4 = reinterpret_cast<float4*>(sH);
#pragma unroll
        for (int i = 0; i < (BM * D / 4) / 256; i++) {
            int idx = i * 256 + tid;           // float4 index within tile
            int r = idx >> 5;                  // D/4 = 32 float4 per row
            int row = row0 + r;
            if (row < N_NODES) {
                sA4[idx] = reinterpret_cast<const float4*>(g_agg)[row * 32 + (idx & 31)];
                sH4[idx] = reinterpret_cast<const float4*>(hin)[(long long)row * 32 + (idx & 31)];
            } else {
                sA4[idx] = make_float4(0.f, 0.f, 0.f, 0.f);
                sH4[idx] = make_float4(0.f, 0.f, 0.f, 0.f);
            }
        }
    }
    __syncthreads();

    unsigned long long acc[8][2];
#pragma unroll
    for (int r = 0; r < 8; r++) { acc[r][0] = 0ull; acc[r][1] = 0ull; }

#pragma unroll 8
    for (int k = 0; k < D; k++) {
        // packed column pairs (cols tx*4+{0,1} and tx*4+{2,3}) — natural 64-bit
        const ulonglong2 wr2 =
            *reinterpret_cast<const ulonglong2*>(&sWrel[k * D + tx * 4]);
        const ulonglong2 wo2 =
            *reinterpret_cast<const ulonglong2*>(&sWroot[k * D + tx * 4]);
#pragma unroll
        for (int r = 0; r < 8; r++) {
            unsigned long long a2 = splat2(sA[(ty * 8 + r) * D + k]);
            unsigned long long h2 = splat2(sH[(ty * 8 + r) * D + k]);
            fma2(acc[r][0], a2, wr2.x);
            fma2(acc[r][0], h2, wo2.x);
            fma2(acc[r][1], a2, wr2.y);
            fma2(acc[r][1], h2, wo2.y);
        }
    }

    // Epilogue: bias + relu, vectorized store
    float4 bias = *reinterpret_cast<const float4*>(&sb[tx * 4]);
#pragma unroll
    for (int r = 0; r < 8; r++) {
        int row = row0 + ty * 8 + r;
        if (row < N_NODES) {
            float2 p0 = unpack2(acc[r][0]);
            float2 p1 = unpack2(acc[r][1]);
            float4 o;
            o.x = fmaxf(p0.x + bias.x, 0.f);
            o.y = fmaxf(p0.y + bias.y, 0.f);
            o.z = fmaxf(p1.x + bias.z, 0.f);
            o.w = fmaxf(p1.y + bias.w, 0.f);
            *reinterpret_cast<float4*>(&hout[(long long)row * D + tx * 4]) = o;
        }
    }
}

// ---------------------------------------------------------------------------
// Pool + head
// ---------------------------------------------------------------------------
__global__ void k_zero_pool() {
    int i = blockIdx.x * blockDim.x + threadIdx.x;
    if (i < N_GRAPHS * D) g_sums[i] = 0.f;
    if (i < N_GRAPHS) g_cnt[i] = 0.f;
}

#define NODES_PER_WARP 4
__global__ __launch_bounds__(256) void k_pool(const float* __restrict__ h,
                                              const int* __restrict__ batch) {
    int gwarp = (blockIdx.x * blockDim.x + threadIdx.x) >> 5;
    int lane = threadIdx.x & 31;
#pragma unroll
    for (int i = 0; i < NODES_PER_WARP; i++) {
        int n = gwarp * NODES_PER_WARP + i;
        if (n >= N_NODES) return;
        int g = batch[n];
        const float4 v = *reinterpret_cast<const float4*>(h + (long long)n * D + lane * 4);
        float* dp = g_sums + g * D + lane * 4;
        asm volatile("red.global.add.v4.f32 [%0], {%1,%2,%3,%4};"
                     :: "l"(dp), "f"(v.x), "f"(v.y), "f"(v.z), "f"(v.w)
                     : "memory");
        if (lane == 0) atomicAdd(&g_cnt[g], 1.0f);
    }
}

__global__ __launch_bounds__(128) void k_head(const float* __restrict__ W1,
                                              const float* __restrict__ b1,
                                              const float* __restrict__ W2,
                                              const float* __restrict__ b2,
                                              float* __restrict__ out) {
    __shared__ float pooled[D];
    __shared__ float t[D];
    int g = blockIdx.x;
    int tid = threadIdx.x;
    float cnt = fmaxf(g_cnt[g], 1.0f);
    pooled[tid] = g_sums[g * D + tid] / cnt;
    __syncthreads();

    float acc = b1[tid];
#pragma unroll 8
    for (int k = 0; k < D; k++) acc += pooled[k] * W1[k * D + tid];
    t[tid] = acc;
    __syncthreads();

    if (tid < OUT_DIM) {
        float o = b2[tid];
#pragma unroll 8
        for (int k = 0; k < D; k++) o += t[k] * W2[k * OUT_DIM + tid];
        out[g * OUT_DIM + tid] = o;
    }
}

// ---------------------------------------------------------------------------
// Launch sequence (graph-capturable: kernel launches only)
// ---------------------------------------------------------------------------
extern "C" void kernel_launch(void* const* d_in, const int* in_sizes, int n_in,
                              void* d_out, int out_size) {
    const float* x = (const float*)d_in[0];
    const int* ei = (const int*)d_in[1];      // int32 (JAX x64 disabled)
    const int* batch = (const int*)d_in[2];   // int32
    const float* Wrel = (const float*)d_in[3];
    const float* brel = (const float*)d_in[4];
    const float* Wroot = (const float*)d_in[5];
    const float* W1 = (const float*)d_in[6];
    const float* b1 = (const float*)d_in[7];
    const float* W2 = (const float*)d_in[8];
    const float* b2 = (const float*)d_in[9];
    float* out = (float*)d_out;

    cudaFuncSetAttribute(k_gemm, cudaFuncAttributeMaxDynamicSharedMemorySize,
                         GEMM_SMEM_BYTES);

    float* hA;
    float* hB;
    cudaGetSymbolAddress((void**)&hA, g_hA);
    cudaGetSymbolAddress((void**)&hB, g_hB);

    const int edge_blocks = (N_EDGES + 255) / 256;
    const int gemm_blocks = (N_NODES + BM - 1) / BM;
    const int gather_blocks = (N_NODES + 7) / 8;          // 8 warps/block
    const int pool_blocks = (N_NODES + 8 * NODES_PER_WARP - 1) / (8 * NODES_PER_WARP);

    // ---- Build CSR (dst -> list of src), once per launch ----
    k_csr_zero<<<(N_NODES + 255) / 256, 256>>>();
    k_hist<<<edge_blocks, 256>>>(ei);
    k_scan1<<<SCAN_BLOCKS, 256>>>();
    k_scan2<<<1, 256>>>();
    k_scan3<<<SCAN_BLOCKS, 256>>>();
    k_fill<<<edge_blocks, 256>>>(ei);

    // Layer 0: x -> hB
    k_gather<<<gather_blocks, 256>>>(x);
    k_gemm<<<gemm_blocks, 256, GEMM_SMEM_BYTES>>>(x, Wrel, brel, Wroot, hB);

    // Layer 1: hB -> hA
    k_gather<<<gather_blocks, 256>>>(hB);
    k_gemm<<<gemm_blocks, 256, GEMM_SMEM_BYTES>>>(hB, Wrel + D * D, brel + D,
                                                  Wroot + D * D, hA);

    // Layer 2: hA -> hB
    k_gather<<<gather_blocks, 256>>>(hA);
    k_gemm<<<gemm_blocks, 256, GEMM_SMEM_BYTES>>>(hA, Wrel + 2 * D * D, brel + 2 * D,
                                                  Wroot + 2 * D * D, hB);

    // Pool + head
    k_zero_pool<<<(N_GRAPHS * D + 255) / 256, 256>>>();
    k_pool<<<pool_blocks, 256>>>(hB, batch);
    k_head<<<N_GRAPHS, 128>>>(W1, b1, W2, b2, out);
}